// round 14
// baseline (speedup 1.0000x reference)
#include <cuda_runtime.h>
#include <math.h>

// Problem constants (shapes are fixed by the dataset)
#define NN 100000
#define EE 1600000
#define F0 512
#define F1 128
#define F2 64

// ---------------- scratch (device globals: no allocation allowed) ----------------
__device__ float g_g1[(size_t)NN * F1];   // (x@W1) * dinv[row]
__device__ float g_h1[(size_t)NN * F1];   // relu layer-1 output
__device__ float g_g2[(size_t)NN * F2];   // (h1@W2) * dinv[row]
__device__ int   g_deg[NN];               // incoming edge count
__device__ float g_dinv[NN];              // rsqrt(deg+1)
__device__ int   g_off[NN + 1];           // CSR offsets by dst
__device__ int   g_cur[NN];               // scatter cursors
__device__ int   g_srcs[EE];              // CSR src node ids (int32)
__device__ int   g_bsum[512];             // block sums for scan
__device__ int   g_is64;                  // 1 if edge_index is int64, 0 if int32

// ---------------- dtype probe: int64 edge data has zero high words ----------------
// Words at odd indices: int64 -> always 0 (values < 2^31, little-endian);
// int32 -> random node ids. P(64 random ids all zero) ~ (1/100000)^64 = 0.
__global__ void probe_k(const int* __restrict__ w) {
    int all_zero = 1;
#pragma unroll
    for (int i = 0; i < 64; i++)
        if (w[2 * i + 1] != 0) all_zero = 0;
    g_is64 = all_zero;
}

// ---------------- small kernels: degree / CSR build ----------------

__global__ void zero_k(int n) {
    int i = blockIdx.x * blockDim.x + threadIdx.x;
    if (i < n) { g_deg[i] = 0; g_cur[i] = 0; }
}

// w = base of edge_index as 32-bit words. E = edge count.
// int32 layout: src=w[e], dst=w[E+e].  int64: src=w[2e], dst=w[2E+2e].
__global__ void hist_k(const int* __restrict__ w, int E) {
    int e = blockIdx.x * blockDim.x + threadIdx.x;
    if (e >= E) return;
    int d = g_is64 ? w[2 * (size_t)E + 2 * (size_t)e] : w[(size_t)E + e];
    atomicAdd(&g_deg[d], 1);
}

// pass 1: per-block (512-wide) sums of deg
__global__ void scan1_k(int n) {
    __shared__ int sh[512];
    int t = threadIdx.x;
    int i = blockIdx.x * 512 + t;
    sh[t] = (i < n) ? g_deg[i] : 0;
    __syncthreads();
    for (int d = 256; d > 0; d >>= 1) {
        if (t < d) sh[t] += sh[t + d];
        __syncthreads();
    }
    if (t == 0) g_bsum[blockIdx.x] = sh[0];
}

// pass 2: exclusive scan of block sums (NB <= 256)
__global__ void scan2_k(int nb) {
    __shared__ int sh[256];
    int t = threadIdx.x;
    int v = (t < nb) ? g_bsum[t] : 0;
    sh[t] = v;
    __syncthreads();
    for (int d = 1; d < 256; d <<= 1) {
        int a = (t >= d) ? sh[t - d] : 0;
        __syncthreads();
        sh[t] += a;
        __syncthreads();
    }
    if (t < nb) g_bsum[t] = sh[t] - v;   // exclusive
}

// pass 3: full exclusive scan -> csr offsets; also dinv
__global__ void scan3_k(int n, int E) {
    __shared__ int sh[512];
    int t = threadIdx.x;
    int i = blockIdx.x * 512 + t;
    int v = (i < n) ? g_deg[i] : 0;
    sh[t] = v;
    __syncthreads();
    for (int d = 1; d < 512; d <<= 1) {
        int a = (t >= d) ? sh[t - d] : 0;
        __syncthreads();
        sh[t] += a;
        __syncthreads();
    }
    int excl = sh[t] - v;
    int off = g_bsum[blockIdx.x] + excl;
    if (i < n) {
        g_off[i] = off;
        g_dinv[i] = rsqrtf((float)(v + 1));
        if (i == n - 1) g_off[n] = off + v;   // == E
    }
}

__global__ void scatter_k(const int* __restrict__ w, int E) {
    int e = blockIdx.x * blockDim.x + threadIdx.x;
    if (e >= E) return;
    int s, d;
    if (g_is64) {
        s = w[2 * (size_t)e];
        d = w[2 * (size_t)E + 2 * (size_t)e];
    } else {
        s = w[e];
        d = w[(size_t)E + e];
    }
    int pos = g_off[d] + atomicAdd(&g_cur[d], 1);
    g_srcs[pos] = s;
}

// ---------------- SGEMM with dinv-scaled epilogue: C[r] = (A@B)[r] * dinv[r] ----------------
// BM=128, BK=16, BN in {128,64}; 8x8 per-thread tile; threads = (BM/8)*(BN/8)
template <int BN, int K>
__global__ void sgemm_scale_k(const float* __restrict__ A, const float* __restrict__ B,
                              float* __restrict__ C, int M) {
    constexpr int BM = 128, BK = 16;
    constexpr int T = (BM / 8) * (BN / 8);
    __shared__ float As[BK][BM];
    __shared__ float Bs[BK][BN];

    const int tid = threadIdx.x;
    const int tx = tid % (BN / 8);
    const int ty = tid / (BN / 8);
    const int row0 = blockIdx.x * BM;

    float acc[8][8];
#pragma unroll
    for (int i = 0; i < 8; i++)
#pragma unroll
        for (int j = 0; j < 8; j++) acc[i][j] = 0.f;

    for (int k0 = 0; k0 < K; k0 += BK) {
        // load A tile (transpose into As[k][m]); coalesced float4 gmem reads
#pragma unroll
        for (int idx = tid; idx < BM * BK / 4; idx += T) {
            int r = idx / (BK / 4);
            int c4 = idx % (BK / 4);
            int g = row0 + r;
            float4 v = make_float4(0.f, 0.f, 0.f, 0.f);
            if (g < M) v = *(const float4*)(A + (size_t)g * K + k0 + c4 * 4);
            As[c4 * 4 + 0][r] = v.x;
            As[c4 * 4 + 1][r] = v.y;
            As[c4 * 4 + 2][r] = v.z;
            As[c4 * 4 + 3][r] = v.w;
        }
        // load B tile (already k-major rows of width BN)
#pragma unroll
        for (int idx = tid; idx < BK * BN / 4; idx += T) {
            int kk = idx / (BN / 4);
            int n4 = idx % (BN / 4);
            *(float4*)&Bs[kk][n4 * 4] = *(const float4*)(B + (size_t)(k0 + kk) * BN + n4 * 4);
        }
        __syncthreads();

#pragma unroll
        for (int k = 0; k < BK; k++) {
            float ra[8], rb[8];
            *(float4*)(ra + 0) = *(const float4*)&As[k][ty * 8 + 0];
            *(float4*)(ra + 4) = *(const float4*)&As[k][ty * 8 + 4];
            *(float4*)(rb + 0) = *(const float4*)&Bs[k][tx * 8 + 0];
            *(float4*)(rb + 4) = *(const float4*)&Bs[k][tx * 8 + 4];
#pragma unroll
            for (int i = 0; i < 8; i++)
#pragma unroll
                for (int j = 0; j < 8; j++) acc[i][j] = fmaf(ra[i], rb[j], acc[i][j]);
        }
        __syncthreads();
    }

#pragma unroll
    for (int i = 0; i < 8; i++) {
        int g = row0 + ty * 8 + i;
        if (g < M) {
            float d = g_dinv[g];
            float4 o;
            o.x = acc[i][0] * d; o.y = acc[i][1] * d; o.z = acc[i][2] * d; o.w = acc[i][3] * d;
            *(float4*)(C + (size_t)g * BN + tx * 8 + 0) = o;
            o.x = acc[i][4] * d; o.y = acc[i][5] * d; o.z = acc[i][6] * d; o.w = acc[i][7] * d;
            *(float4*)(C + (size_t)g * BN + tx * 8 + 4) = o;
        }
    }
}

// ---------------- layer-1 aggregation: warp per node, 128 feats = float4/lane ----------------
__global__ void agg1_k(const float* __restrict__ b1, int n) {
    int node = (blockIdx.x * blockDim.x + threadIdx.x) >> 5;
    int lane = threadIdx.x & 31;
    if (node >= n) return;
    int beg = g_off[node], end = g_off[node + 1];
    float4 acc = make_float4(0.f, 0.f, 0.f, 0.f);
    for (int e = beg; e < end; e++) {
        int s = __ldg(&g_srcs[e]);
        float4 v = __ldg((const float4*)&g_g1[(size_t)s * F1 + lane * 4]);
        acc.x += v.x; acc.y += v.y; acc.z += v.z; acc.w += v.w;
    }
    float d = g_dinv[node];
    float4 self = *(const float4*)&g_g1[(size_t)node * F1 + lane * 4];
    float4 bb = __ldg((const float4*)&b1[lane * 4]);
    float4 o;
    o.x = fmaxf(fmaf(d, acc.x + self.x, bb.x), 0.f);
    o.y = fmaxf(fmaf(d, acc.y + self.y, bb.y), 0.f);
    o.z = fmaxf(fmaf(d, acc.z + self.z, bb.z), 0.f);
    o.w = fmaxf(fmaf(d, acc.w + self.w, bb.w), 0.f);
    *(float4*)&g_h1[(size_t)node * F1 + lane * 4] = o;
}

// ---------------- layer-2 aggregation + fused log_softmax: warp per node, 64 feats = float2/lane ----------------
__global__ void agg2_k(const float* __restrict__ b2, float* __restrict__ out, int n) {
    int node = (blockIdx.x * blockDim.x + threadIdx.x) >> 5;
    int lane = threadIdx.x & 31;
    if (node >= n) return;
    int beg = g_off[node], end = g_off[node + 1];
    float2 acc = make_float2(0.f, 0.f);
    for (int e = beg; e < end; e++) {
        int s = __ldg(&g_srcs[e]);
        float2 v = __ldg((const float2*)&g_g2[(size_t)s * F2 + lane * 2]);
        acc.x += v.x; acc.y += v.y;
    }
    float d = g_dinv[node];
    float2 self = *(const float2*)&g_g2[(size_t)node * F2 + lane * 2];
    float2 bb = __ldg((const float2*)&b2[lane * 2]);
    float v0 = fmaf(d, acc.x + self.x, bb.x);
    float v1 = fmaf(d, acc.y + self.y, bb.y);

    // warp-level log_softmax over 64 values
    float m = fmaxf(v0, v1);
#pragma unroll
    for (int o = 16; o > 0; o >>= 1) m = fmaxf(m, __shfl_xor_sync(0xffffffffu, m, o));
    float s = expf(v0 - m) + expf(v1 - m);
#pragma unroll
    for (int o = 16; o > 0; o >>= 1) s += __shfl_xor_sync(0xffffffffu, s, o);
    float lse = m + logf(s);

    float2 r;
    r.x = v0 - lse;
    r.y = v1 - lse;
    *(float2*)&out[(size_t)node * F2 + lane * 2] = r;
}

// ---------------- launch ----------------
extern "C" void kernel_launch(void* const* d_in, const int* in_sizes, int n_in,
                              void* d_out, int out_size) {
    const float* x  = (const float*)d_in[0];
    const int*   ew = (const int*)d_in[1];   // edge_index as 32-bit words (dtype probed on-device)
    const float* W1 = (const float*)d_in[2];
    const float* b1 = (const float*)d_in[3];
    const float* W2 = (const float*)d_in[4];
    const float* b2 = (const float*)d_in[5];
    float*       out = (float*)d_out;

    const int M = in_sizes[0] / F0;       // 100000
    const int E = in_sizes[1] / 2;        // 1600000 (element count is dtype-independent)
    const int NB = (M + 511) / 512;       // <= 256 required by scan2_k

    float *p_g1, *p_h1, *p_g2;
    cudaGetSymbolAddress((void**)&p_g1, g_g1);
    cudaGetSymbolAddress((void**)&p_h1, g_h1);
    cudaGetSymbolAddress((void**)&p_g2, g_g2);

    // dtype probe + degree + CSR by dst
    probe_k<<<1, 1>>>(ew);
    zero_k<<<(M + 255) / 256, 256>>>(M);
    hist_k<<<(E + 255) / 256, 256>>>(ew, E);
    scan1_k<<<NB, 512>>>(M);
    scan2_k<<<1, 256>>>(NB);
    scan3_k<<<NB, 512>>>(M, E);
    scatter_k<<<(E + 255) / 256, 256>>>(ew, E);

    // layer 1: g1 = (x@W1)*dinv ; h1 = relu(dinv*(sum g1[src] + g1) + b1)
    sgemm_scale_k<F1, F0><<<(M + 127) / 128, 256>>>(x, W1, p_g1, M);
    agg1_k<<<(M * 32 + 255) / 256, 256>>>(b1, M);

    // layer 2: g2 = (h1@W2)*dinv ; out = log_softmax(dinv*(sum g2[src] + g2) + b2)
    sgemm_scale_k<F2, F1><<<(M + 127) / 128, 128>>>(p_h1, W2, p_g2, M);
    agg2_k<<<(M * 32 + 255) / 256, 256>>>(b2, out, M);
}

// round 15
// speedup vs baseline: 1.0002x; 1.0002x over previous
#include <cuda_runtime.h>
#include <math.h>

// Problem constants (shapes are fixed by the dataset)
#define NN 100000
#define EE 1600000
#define F0 512
#define F1 128
#define F2 64

// ---------------- scratch (device globals: no allocation allowed) ----------------
__device__ float g_g1[(size_t)NN * F1];   // (x@W1) * dinv[row]
__device__ float g_h1[(size_t)NN * F1];   // relu layer-1 output
__device__ float g_g2[(size_t)NN * F2];   // (h1@W2) * dinv[row]
__device__ int   g_deg[NN];               // incoming edge count
__device__ float g_dinv[NN];              // rsqrt(deg+1)
__device__ int   g_off[NN + 1];           // CSR offsets by dst
__device__ int   g_cur[NN];               // scatter cursors
__device__ int   g_srcs[EE];              // CSR src node ids (int32)
__device__ int   g_bsum[512];             // block sums for scan
__device__ int   g_is64;                  // 1 if edge_index is int64, 0 if int32

// ---------------- dtype probe: int64 edge data has zero high words ----------------
// Words at odd indices: int64 -> always 0 (values < 2^31, little-endian);
// int32 -> random node ids. P(64 random ids all zero) ~ (1/100000)^64 = 0.
__global__ void probe_k(const int* __restrict__ w) {
    int all_zero = 1;
#pragma unroll
    for (int i = 0; i < 64; i++)
        if (w[2 * i + 1] != 0) all_zero = 0;
    g_is64 = all_zero;
}

// ---------------- small kernels: degree / CSR build ----------------

__global__ void zero_k(int n) {
    int i = blockIdx.x * blockDim.x + threadIdx.x;
    if (i < n) { g_deg[i] = 0; g_cur[i] = 0; }
}

// w = base of edge_index as 32-bit words. E = edge count.
// int32 layout: src=w[e], dst=w[E+e].  int64: src=w[2e], dst=w[2E+2e].
__global__ void hist_k(const int* __restrict__ w, int E) {
    int e = blockIdx.x * blockDim.x + threadIdx.x;
    if (e >= E) return;
    int d = g_is64 ? w[2 * (size_t)E + 2 * (size_t)e] : w[(size_t)E + e];
    atomicAdd(&g_deg[d], 1);
}

// pass 1: per-block (512-wide) sums of deg
__global__ void scan1_k(int n) {
    __shared__ int sh[512];
    int t = threadIdx.x;
    int i = blockIdx.x * 512 + t;
    sh[t] = (i < n) ? g_deg[i] : 0;
    __syncthreads();
    for (int d = 256; d > 0; d >>= 1) {
        if (t < d) sh[t] += sh[t + d];
        __syncthreads();
    }
    if (t == 0) g_bsum[blockIdx.x] = sh[0];
}

// pass 2: exclusive scan of block sums (NB <= 256)
__global__ void scan2_k(int nb) {
    __shared__ int sh[256];
    int t = threadIdx.x;
    int v = (t < nb) ? g_bsum[t] : 0;
    sh[t] = v;
    __syncthreads();
    for (int d = 1; d < 256; d <<= 1) {
        int a = (t >= d) ? sh[t - d] : 0;
        __syncthreads();
        sh[t] += a;
        __syncthreads();
    }
    if (t < nb) g_bsum[t] = sh[t] - v;   // exclusive
}

// pass 3: full exclusive scan -> csr offsets; also dinv
__global__ void scan3_k(int n, int E) {
    __shared__ int sh[512];
    int t = threadIdx.x;
    int i = blockIdx.x * 512 + t;
    int v = (i < n) ? g_deg[i] : 0;
    sh[t] = v;
    __syncthreads();
    for (int d = 1; d < 512; d <<= 1) {
        int a = (t >= d) ? sh[t - d] : 0;
        __syncthreads();
        sh[t] += a;
        __syncthreads();
    }
    int excl = sh[t] - v;
    int off = g_bsum[blockIdx.x] + excl;
    if (i < n) {
        g_off[i] = off;
        g_dinv[i] = rsqrtf((float)(v + 1));
        if (i == n - 1) g_off[n] = off + v;   // == E
    }
}

__global__ void scatter_k(const int* __restrict__ w, int E) {
    int e = blockIdx.x * blockDim.x + threadIdx.x;
    if (e >= E) return;
    int s, d;
    if (g_is64) {
        s = w[2 * (size_t)e];
        d = w[2 * (size_t)E + 2 * (size_t)e];
    } else {
        s = w[e];
        d = w[(size_t)E + e];
    }
    int pos = g_off[d] + atomicAdd(&g_cur[d], 1);
    g_srcs[pos] = s;
}

// ---------------- SGEMM with dinv-scaled epilogue: C[r] = (A@B)[r] * dinv[r] ----------------
// BM=128, BK=16, BN in {128,64}; 8x8 per-thread tile; threads = (BM/8)*(BN/8)
template <int BN, int K>
__global__ void sgemm_scale_k(const float* __restrict__ A, const float* __restrict__ B,
                              float* __restrict__ C, int M) {
    constexpr int BM = 128, BK = 16;
    constexpr int T = (BM / 8) * (BN / 8);
    __shared__ float As[BK][BM];
    __shared__ float Bs[BK][BN];

    const int tid = threadIdx.x;
    const int tx = tid % (BN / 8);
    const int ty = tid / (BN / 8);
    const int row0 = blockIdx.x * BM;

    float acc[8][8];
#pragma unroll
    for (int i = 0; i < 8; i++)
#pragma unroll
        for (int j = 0; j < 8; j++) acc[i][j] = 0.f;

    for (int k0 = 0; k0 < K; k0 += BK) {
        // load A tile (transpose into As[k][m]); coalesced float4 gmem reads
#pragma unroll
        for (int idx = tid; idx < BM * BK / 4; idx += T) {
            int r = idx / (BK / 4);
            int c4 = idx % (BK / 4);
            int g = row0 + r;
            float4 v = make_float4(0.f, 0.f, 0.f, 0.f);
            if (g < M) v = *(const float4*)(A + (size_t)g * K + k0 + c4 * 4);
            As[c4 * 4 + 0][r] = v.x;
            As[c4 * 4 + 1][r] = v.y;
            As[c4 * 4 + 2][r] = v.z;
            As[c4 * 4 + 3][r] = v.w;
        }
        // load B tile (already k-major rows of width BN)
#pragma unroll
        for (int idx = tid; idx < BK * BN / 4; idx += T) {
            int kk = idx / (BN / 4);
            int n4 = idx % (BN / 4);
            *(float4*)&Bs[kk][n4 * 4] = *(const float4*)(B + (size_t)(k0 + kk) * BN + n4 * 4);
        }
        __syncthreads();

#pragma unroll
        for (int k = 0; k < BK; k++) {
            float ra[8], rb[8];
            *(float4*)(ra + 0) = *(const float4*)&As[k][ty * 8 + 0];
            *(float4*)(ra + 4) = *(const float4*)&As[k][ty * 8 + 4];
            *(float4*)(rb + 0) = *(const float4*)&Bs[k][tx * 8 + 0];
            *(float4*)(rb + 4) = *(const float4*)&Bs[k][tx * 8 + 4];
#pragma unroll
            for (int i = 0; i < 8; i++)
#pragma unroll
                for (int j = 0; j < 8; j++) acc[i][j] = fmaf(ra[i], rb[j], acc[i][j]);
        }
        __syncthreads();
    }

#pragma unroll
    for (int i = 0; i < 8; i++) {
        int g = row0 + ty * 8 + i;
        if (g < M) {
            float d = g_dinv[g];
            float4 o;
            o.x = acc[i][0] * d; o.y = acc[i][1] * d; o.z = acc[i][2] * d; o.w = acc[i][3] * d;
            *(float4*)(C + (size_t)g * BN + tx * 8 + 0) = o;
            o.x = acc[i][4] * d; o.y = acc[i][5] * d; o.z = acc[i][6] * d; o.w = acc[i][7] * d;
            *(float4*)(C + (size_t)g * BN + tx * 8 + 4) = o;
        }
    }
}

// ---------------- layer-1 aggregation: warp per node, 128 feats = float4/lane ----------------
__global__ void agg1_k(const float* __restrict__ b1, int n) {
    int node = (blockIdx.x * blockDim.x + threadIdx.x) >> 5;
    int lane = threadIdx.x & 31;
    if (node >= n) return;
    int beg = g_off[node], end = g_off[node + 1];
    float4 acc = make_float4(0.f, 0.f, 0.f, 0.f);
    for (int e = beg; e < end; e++) {
        int s = __ldg(&g_srcs[e]);
        float4 v = __ldg((const float4*)&g_g1[(size_t)s * F1 + lane * 4]);
        acc.x += v.x; acc.y += v.y; acc.z += v.z; acc.w += v.w;
    }
    float d = g_dinv[node];
    float4 self = *(const float4*)&g_g1[(size_t)node * F1 + lane * 4];
    float4 bb = __ldg((const float4*)&b1[lane * 4]);
    float4 o;
    o.x = fmaxf(fmaf(d, acc.x + self.x, bb.x), 0.f);
    o.y = fmaxf(fmaf(d, acc.y + self.y, bb.y), 0.f);
    o.z = fmaxf(fmaf(d, acc.z + self.z, bb.z), 0.f);
    o.w = fmaxf(fmaf(d, acc.w + self.w, bb.w), 0.f);
    *(float4*)&g_h1[(size_t)node * F1 + lane * 4] = o;
}

// ---------------- layer-2 aggregation + fused log_softmax: warp per node, 64 feats = float2/lane ----------------
__global__ void agg2_k(const float* __restrict__ b2, float* __restrict__ out, int n) {
    int node = (blockIdx.x * blockDim.x + threadIdx.x) >> 5;
    int lane = threadIdx.x & 31;
    if (node >= n) return;
    int beg = g_off[node], end = g_off[node + 1];
    float2 acc = make_float2(0.f, 0.f);
    for (int e = beg; e < end; e++) {
        int s = __ldg(&g_srcs[e]);
        float2 v = __ldg((const float2*)&g_g2[(size_t)s * F2 + lane * 2]);
        acc.x += v.x; acc.y += v.y;
    }
    float d = g_dinv[node];
    float2 self = *(const float2*)&g_g2[(size_t)node * F2 + lane * 2];
    float2 bb = __ldg((const float2*)&b2[lane * 2]);
    float v0 = fmaf(d, acc.x + self.x, bb.x);
    float v1 = fmaf(d, acc.y + self.y, bb.y);

    // warp-level log_softmax over 64 values
    float m = fmaxf(v0, v1);
#pragma unroll
    for (int o = 16; o > 0; o >>= 1) m = fmaxf(m, __shfl_xor_sync(0xffffffffu, m, o));
    float s = expf(v0 - m) + expf(v1 - m);
#pragma unroll
    for (int o = 16; o > 0; o >>= 1) s += __shfl_xor_sync(0xffffffffu, s, o);
    float lse = m + logf(s);

    float2 r;
    r.x = v0 - lse;
    r.y = v1 - lse;
    *(float2*)&out[(size_t)node * F2 + lane * 2] = r;
}

// ---------------- launch ----------------
extern "C" void kernel_launch(void* const* d_in, const int* in_sizes, int n_in,
                              void* d_out, int out_size) {
    const float* x  = (const float*)d_in[0];
    const int*   ew = (const int*)d_in[1];   // edge_index as 32-bit words (dtype probed on-device)
    const float* W1 = (const float*)d_in[2];
    const float* b1 = (const float*)d_in[3];
    const float* W2 = (const float*)d_in[4];
    const float* b2 = (const float*)d_in[5];
    float*       out = (float*)d_out;

    const int M = in_sizes[0] / F0;       // 100000
    const int E = in_sizes[1] / 2;        // 1600000 (element count is dtype-independent)
    const int NB = (M + 511) / 512;       // <= 256 required by scan2_k

    float *p_g1, *p_h1, *p_g2;
    cudaGetSymbolAddress((void**)&p_g1, g_g1);
    cudaGetSymbolAddress((void**)&p_h1, g_h1);
    cudaGetSymbolAddress((void**)&p_g2, g_g2);

    // dtype probe + degree + CSR by dst
    probe_k<<<1, 1>>>(ew);
    zero_k<<<(M + 255) / 256, 256>>>(M);
    hist_k<<<(E + 255) / 256, 256>>>(ew, E);
    scan1_k<<<NB, 512>>>(M);
    scan2_k<<<1, 256>>>(NB);
    scan3_k<<<NB, 512>>>(M, E);
    scatter_k<<<(E + 255) / 256, 256>>>(ew, E);

    // layer 1: g1 = (x@W1)*dinv ; h1 = relu(dinv*(sum g1[src] + g1) + b1)
    sgemm_scale_k<F1, F0><<<(M + 127) / 128, 256>>>(x, W1, p_g1, M);
    agg1_k<<<(M * 32 + 255) / 256, 256>>>(b1, M);

    // layer 2: g2 = (h1@W2)*dinv ; out = log_softmax(dinv*(sum g2[src] + g2) + b2)
    sgemm_scale_k<F2, F1><<<(M + 127) / 128, 128>>>(p_h1, W2, p_g2, M);
    agg2_k<<<(M * 32 + 255) / 256, 256>>>(b2, out, M);
}